// round 12
// baseline (speedup 1.0000x reference)
#include <cuda_runtime.h>
#include <math.h>

// Problem constants
#define BB 32
#define SS 52
#define AA 5
#define CC 80
#define TT 50
#define PD (AA * (5 + CC))            // 425
#define NROWS (BB * SS * SS)          // 86,528
#define NCONF (NROWS * AA)            // 432,640
#define GG 2                          // confs per thread (front-batched)
#define NBLK_NOBJ (NCONF / (256 * GG))  // 845 (exact: 432640 = 845*512)
#define NBLOCKS (NBLK_NOBJ + BB)      // 877 : 0..844 noobj, 845..876 targets

// Anchors (w, h)
__device__ __constant__ float c_anchors[AA * 2] = {
    1.3221f, 1.73145f,
    3.19275f, 4.00944f,
    5.05587f, 8.09892f,
    9.47112f, 4.84053f,
    11.2364f, 10.0071f
};

// Partials. Target blocks write rows 0/1 (indexed 0..31) and their g_part2
// slot; noobj blocks write only g_part2. All read slots overwritten every
// launch -> no zeroing needed.
__device__ float g_part0[BB];
__device__ float g_part1[BB];
__device__ float g_part2[NBLOCKS];
__device__ unsigned int g_ticket;   // static 0; finalizer resets

__device__ __forceinline__ float sigmoidf_(float x) {
    return 1.0f / (1.0f + __expf(-x));
}

__device__ __forceinline__ float warp_sum(float v) {
    #pragma unroll
    for (int o = 16; o > 0; o >>= 1) v += __shfl_down_sync(0xFFFFFFFFu, v, o);
    return v;
}
__device__ __forceinline__ double warp_sum_d(double v) {
    #pragma unroll
    for (int o = 16; o > 0; o >>= 1) v += __shfl_down_sync(0xFFFFFFFFu, v, o);
    return v;
}

__global__ __launch_bounds__(256) void k_fused(const float* __restrict__ pred,
                                               const float* __restrict__ tgt,
                                               float* __restrict__ out, int out_size) {
    __shared__ float s_t[TT * 5];       // target blocks only
    __shared__ int   s_cell[TT];
    __shared__ int   s_loser[TT];
    __shared__ float s_red[3][8];
    __shared__ double s_redd[3][8];
    __shared__ unsigned int s_last;

    const int tid = threadIdx.x;
    const int bid = blockIdx.x;
    const int lane = tid & 31, warp = tid >> 5;
    float a0 = 0.0f, a1 = 0.0f, a2 = 0.0f;   // coord, obj, conf^2 net

    if (bid >= NBLK_NOBJ) {
        const int b = bid - NBLK_NOBJ;    // batch index 0..31
        if (tid < TT * 5) s_t[tid] = tgt[b * TT * 5 + tid];
        if (tid < TT) s_loser[tid] = 0;
        __syncthreads();

        // Per-target cell (threads 0..49)
        if (tid < TT) {
            const float* tr = &s_t[tid * 5];
            float gtw = tr[2] * (float)SS;
            float gth = tr[3] * (float)SS;
            float best = -1.0f;
            int best_a = 0;
            #pragma unroll
            for (int a = 0; a < AA; a++) {
                float aw = c_anchors[a * 2], ah = c_anchors[a * 2 + 1];
                float inter = fminf(gtw, aw) * fminf(gth, ah);
                float uni = gtw * gth + aw * ah - inter;
                float iou = (uni > 0.0f) ? (inter / uni) : 0.0f;
                if (iou > best) { best = iou; best_a = a; }  // first max wins
            }
            int gi = (int)(tr[0] * (float)SS);
            int gj = (int)(tr[1] * (float)SS);
            s_cell[tid] = (best_a * SS + gj) * SS + gi;      // batch-local cell id
        }
        __syncthreads();

        // Parallel last-wins: pair (t,u), u>t, same cell => t loses.
        for (int p = tid; p < TT * TT; p += 256) {
            int t = p / TT, u = p - t * TT;
            if (u > t && s_cell[u] == s_cell[t]) s_loser[t] = 1;
        }
        __syncthreads();

        // Winners gather + losses (threads 0..49)
        if (tid < TT && !s_loser[tid]) {
            const float* tr = &s_t[tid * 5];
            float gx = tr[0], gy = tr[1];
            float gtw = tr[2] * (float)SS;
            float gth = tr[3] * (float)SS;
            int myc = s_cell[tid];
            int gi = myc % SS;
            int gj = (myc / SS) % SS;
            int best_a = myc / (SS * SS);

            const float* p = pred + (((size_t)b * SS + gj) * SS + gi) * PD + best_a * (5 + CC);
            float tx = p[0], ty = p[1], tw = p[2], th = p[3], score = p[4];
            float pbx = sigmoidf_(tx);
            float pby = sigmoidf_(ty);
            float pbw = __expf(tw) * c_anchors[best_a * 2];
            float pbh = __expf(th) * c_anchors[best_a * 2 + 1];
            float conf = sigmoidf_(score);

            float ggx = gx * (float)SS - (float)gi;
            float ggy = gy * (float)SS - (float)gj;

            float cx1 = ggx + (float)gi, cy1 = ggy + (float)gj;
            float cx2 = pbx + (float)gi, cy2 = pby + (float)gj;
            float ix = fmaxf(0.0f, fminf(cx1 + gtw * 0.5f, cx2 + pbw * 0.5f)
                                 - fmaxf(cx1 - gtw * 0.5f, cx2 - pbw * 0.5f));
            float iy = fmaxf(0.0f, fminf(cy1 + gth * 0.5f, cy2 + pbh * 0.5f)
                                 - fmaxf(cy1 - gth * 0.5f, cy2 - pbh * 0.5f));
            float inter = ix * iy;
            float uni = gtw * gth + pbw * pbh - inter;
            float iou = (uni > 0.0f) ? (inter / uni) : 0.0f;

            const float eps = 1e-6f;
            float d1 = pbx - ggx, d2 = pby - ggy;
            float s1 = sqrtf(pbw + eps) - sqrtf(gtw + eps);
            float s2 = sqrtf(pbh + eps) - sqrtf(gth + eps);
            a0 = d1 * d1 + d2 * d2 + s1 * s1 + s2 * s2;
            float od = iou - conf;
            a1 = od * od;
            a2 = -conf * conf;      // remove obj cell from no-obj sum
        }
    } else {
        // No-obj: GG front-batched independent loads per thread.
        // Default caching: conf lines (55 MB) stay L2-resident across graph
        // replays -> warm-replay loads are L2 hits.
        int base = bid * (256 * GG) + tid;      // stride-256 within block
        float s[GG];
        #pragma unroll
        for (int g = 0; g < GG; g++) {
            int n = base + g * 256;             // < NCONF (exact tiling)
            int r = n / AA;
            int a = n - r * AA;
            s[g] = pred[(size_t)r * PD + a * (5 + CC) + 4];
        }
        #pragma unroll
        for (int g = 0; g < GG; g++) {
            float conf = sigmoidf_(s[g]);
            a2 += conf * conf;
        }
    }

    // Block reduction -> per-block partial slots (no atomics).
    // No-obj blocks only carry a2 -> slim path.
    float w2 = warp_sum(a2);
    if (bid >= NBLK_NOBJ) {
        float w0 = warp_sum(a0), w1 = warp_sum(a1);
        if (lane == 0) { s_red[0][warp] = w0; s_red[1][warp] = w1; }
    }
    if (lane == 0) s_red[2][warp] = w2;
    __syncthreads();
    if (tid == 0) {
        float b2 = 0.0f;
        #pragma unroll
        for (int w = 0; w < 8; w++) b2 += s_red[2][w];
        if (bid >= NBLK_NOBJ) {
            float b0 = 0.0f, b1 = 0.0f;
            #pragma unroll
            for (int w = 0; w < 8; w++) { b0 += s_red[0][w]; b1 += s_red[1][w]; }
            g_part0[bid - NBLK_NOBJ] = b0;
            g_part1[bid - NBLK_NOBJ] = b1;
        }
        g_part2[bid] = b2;
        __threadfence();
        unsigned int t = atomicAdd(&g_ticket, 1u);
        s_last = (t == (unsigned int)(gridDim.x - 1)) ? 1u : 0u;
    }
    __syncthreads();

    // Parallel finalize in last-arriving block (fixed-order -> deterministic)
    if (s_last) {
        double v0 = 0.0, v1 = 0.0, v2 = 0.0;
        if (tid < BB) { v0 = (double)g_part0[tid]; v1 = (double)g_part1[tid]; }
        for (int i = tid; i < NBLOCKS; i += 256) v2 += (double)g_part2[i];
        v0 = warp_sum_d(v0); v1 = warp_sum_d(v1); v2 = warp_sum_d(v2);
        if (lane == 0) { s_redd[0][warp] = v0; s_redd[1][warp] = v1; s_redd[2][warp] = v2; }
        __syncthreads();
        if (tid == 0) {
            double c0 = 0.0, c1 = 0.0, c2 = 0.0;
            #pragma unroll
            for (int w = 0; w < 8; w++) { c0 += s_redd[0][w]; c1 += s_redd[1][w]; c2 += s_redd[2][w]; }
            double loss_coord = 5.0 * c0;
            double loss_noobj = 0.5 * c2;
            double total = 5.0 * loss_coord + c1 + 0.5 * loss_noobj;
            if (out_size > 0) out[0] = (float)total;
            if (out_size > 1) out[1] = (float)loss_coord;
            if (out_size > 2) out[2] = (float)(c1 + loss_noobj);
            g_ticket = 0;   // reset for next graph replay
        }
    }
}

extern "C" void kernel_launch(void* const* d_in, const int* in_sizes, int n_in,
                              void* d_out, int out_size) {
    const float* pred = (const float*)d_in[0];   // [32,52,52,425]
    const float* tgt  = (const float*)d_in[1];   // [32,50,5]
    float* out = (float*)d_out;

    k_fused<<<NBLOCKS, 256>>>(pred, tgt, out, out_size);
}

// round 13
// speedup vs baseline: 1.0074x; 1.0074x over previous
#include <cuda_runtime.h>
#include <math.h>

// Problem constants
#define BB 32
#define SS 52
#define AA 5
#define CC 80
#define TT 50
#define PD (AA * (5 + CC))            // 425
#define NROWS (BB * SS * SS)          // 86,528
#define NCONF (NROWS * AA)            // 432,640
#define GG 8                          // confs per thread (front-batched)
#define NBLK_NOBJ ((NCONF + 256*GG - 1) / (256 * GG))  // 212
#define NBLOCKS (NBLK_NOBJ + BB)      // 244 : 0..211 noobj, 212..243 targets

// Anchors (w, h)
__device__ __constant__ float c_anchors[AA * 2] = {
    1.3221f, 1.73145f,
    3.19275f, 4.00944f,
    5.05587f, 8.09892f,
    9.47112f, 4.84053f,
    11.2364f, 10.0071f
};

// Partials. Target blocks write rows 0/1 (indexed 0..31) and their g_part2
// slot; noobj blocks write only g_part2. All read slots overwritten every
// launch -> no zeroing needed.
__device__ float g_part0[BB];
__device__ float g_part1[BB];
__device__ float g_part2[NBLOCKS];
__device__ unsigned int g_ticket;   // static 0; finalizer resets

__device__ __forceinline__ float sigmoidf_(float x) {
    return 1.0f / (1.0f + __expf(-x));
}

__device__ __forceinline__ float warp_sum(float v) {
    #pragma unroll
    for (int o = 16; o > 0; o >>= 1) v += __shfl_down_sync(0xFFFFFFFFu, v, o);
    return v;
}
__device__ __forceinline__ double warp_sum_d(double v) {
    #pragma unroll
    for (int o = 16; o > 0; o >>= 1) v += __shfl_down_sync(0xFFFFFFFFu, v, o);
    return v;
}

__global__ __launch_bounds__(256) void k_fused(const float* __restrict__ pred,
                                               const float* __restrict__ tgt,
                                               float* __restrict__ out, int out_size) {
    __shared__ float s_t[TT * 5];       // target blocks only
    __shared__ int   s_cell[TT];
    __shared__ int   s_loser[TT];
    __shared__ float s_red[3][8];
    __shared__ double s_redd[3][8];
    __shared__ unsigned int s_last;

    const int tid = threadIdx.x;
    const int bid = blockIdx.x;
    const int lane = tid & 31, warp = tid >> 5;
    float a0 = 0.0f, a1 = 0.0f, a2 = 0.0f;   // coord, obj, conf^2 net

    if (bid >= NBLK_NOBJ) {
        const int b = bid - NBLK_NOBJ;    // batch index 0..31
        if (tid < TT * 5) s_t[tid] = tgt[b * TT * 5 + tid];
        if (tid < TT) s_loser[tid] = 0;
        __syncthreads();

        // Per-target cell (threads 0..49)
        if (tid < TT) {
            const float* tr = &s_t[tid * 5];
            float gtw = tr[2] * (float)SS;
            float gth = tr[3] * (float)SS;
            float best = -1.0f;
            int best_a = 0;
            #pragma unroll
            for (int a = 0; a < AA; a++) {
                float aw = c_anchors[a * 2], ah = c_anchors[a * 2 + 1];
                float inter = fminf(gtw, aw) * fminf(gth, ah);
                float uni = gtw * gth + aw * ah - inter;
                float iou = (uni > 0.0f) ? (inter / uni) : 0.0f;
                if (iou > best) { best = iou; best_a = a; }  // first max wins
            }
            int gi = (int)(tr[0] * (float)SS);
            int gj = (int)(tr[1] * (float)SS);
            s_cell[tid] = (best_a * SS + gj) * SS + gi;      // batch-local cell id
        }
        __syncthreads();

        // Parallel last-wins: pair (t,u), u>t, same cell => t loses.
        for (int p = tid; p < TT * TT; p += 256) {
            int t = p / TT, u = p - t * TT;
            if (u > t && s_cell[u] == s_cell[t]) s_loser[t] = 1;
        }
        __syncthreads();

        // Winners gather + losses (threads 0..49)
        if (tid < TT && !s_loser[tid]) {
            const float* tr = &s_t[tid * 5];
            float gx = tr[0], gy = tr[1];
            float gtw = tr[2] * (float)SS;
            float gth = tr[3] * (float)SS;
            int myc = s_cell[tid];
            int gi = myc % SS;
            int gj = (myc / SS) % SS;
            int best_a = myc / (SS * SS);

            const float* p = pred + (((size_t)b * SS + gj) * SS + gi) * PD + best_a * (5 + CC);
            float tx = p[0], ty = p[1], tw = p[2], th = p[3], score = p[4];
            float pbx = sigmoidf_(tx);
            float pby = sigmoidf_(ty);
            float pbw = __expf(tw) * c_anchors[best_a * 2];
            float pbh = __expf(th) * c_anchors[best_a * 2 + 1];
            float conf = sigmoidf_(score);

            float ggx = gx * (float)SS - (float)gi;
            float ggy = gy * (float)SS - (float)gj;

            float cx1 = ggx + (float)gi, cy1 = ggy + (float)gj;
            float cx2 = pbx + (float)gi, cy2 = pby + (float)gj;
            float ix = fmaxf(0.0f, fminf(cx1 + gtw * 0.5f, cx2 + pbw * 0.5f)
                                 - fmaxf(cx1 - gtw * 0.5f, cx2 - pbw * 0.5f));
            float iy = fmaxf(0.0f, fminf(cy1 + gth * 0.5f, cy2 + pbh * 0.5f)
                                 - fmaxf(cy1 - gth * 0.5f, cy2 - pbh * 0.5f));
            float inter = ix * iy;
            float uni = gtw * gth + pbw * pbh - inter;
            float iou = (uni > 0.0f) ? (inter / uni) : 0.0f;

            const float eps = 1e-6f;
            float d1 = pbx - ggx, d2 = pby - ggy;
            float s1 = sqrtf(pbw + eps) - sqrtf(gtw + eps);
            float s2 = sqrtf(pbh + eps) - sqrtf(gth + eps);
            a0 = d1 * d1 + d2 * d2 + s1 * s1 + s2 * s2;
            float od = iou - conf;
            a1 = od * od;
            a2 = -conf * conf;      // remove obj cell from no-obj sum
        }
    } else {
        // No-obj: GG front-batched independent streaming loads per thread.
        // All GG loads issued back-to-back (max MLP) before any dependent math.
        int base = bid * (256 * GG) + tid;      // stride-256 within block
        float s[GG];
        #pragma unroll
        for (int g = 0; g < GG; g++) {
            int n = base + g * 256;
            int r = n / AA;
            int a = n - r * AA;
            s[g] = (n < NCONF) ? __ldcs(&pred[(size_t)r * PD + a * (5 + CC) + 4])
                               : 0.0f;
        }
        #pragma unroll
        for (int g = 0; g < GG; g++) {
            int n = base + g * 256;
            if (n < NCONF) {
                float conf = sigmoidf_(s[g]);
                a2 += conf * conf;
            }
        }
    }

    // Block reduction -> per-block partial slots (no atomics).
    // No-obj blocks only carry a2 -> slim path.
    float w2 = warp_sum(a2);
    if (bid >= NBLK_NOBJ) {
        float w0 = warp_sum(a0), w1 = warp_sum(a1);
        if (lane == 0) { s_red[0][warp] = w0; s_red[1][warp] = w1; }
    }
    if (lane == 0) s_red[2][warp] = w2;
    __syncthreads();
    if (tid == 0) {
        float b2 = 0.0f;
        #pragma unroll
        for (int w = 0; w < 8; w++) b2 += s_red[2][w];
        if (bid >= NBLK_NOBJ) {
            float b0 = 0.0f, b1 = 0.0f;
            #pragma unroll
            for (int w = 0; w < 8; w++) { b0 += s_red[0][w]; b1 += s_red[1][w]; }
            g_part0[bid - NBLK_NOBJ] = b0;
            g_part1[bid - NBLK_NOBJ] = b1;
        }
        g_part2[bid] = b2;
        __threadfence();
        unsigned int t = atomicAdd(&g_ticket, 1u);
        s_last = (t == (unsigned int)(gridDim.x - 1)) ? 1u : 0u;
    }
    __syncthreads();

    // Parallel finalize in last-arriving block (fixed-order -> deterministic)
    if (s_last) {
        double v0 = 0.0, v1 = 0.0, v2 = 0.0;
        if (tid < BB) { v0 = (double)g_part0[tid]; v1 = (double)g_part1[tid]; }
        for (int i = tid; i < NBLOCKS; i += 256) v2 += (double)g_part2[i];
        v0 = warp_sum_d(v0); v1 = warp_sum_d(v1); v2 = warp_sum_d(v2);
        if (lane == 0) { s_redd[0][warp] = v0; s_redd[1][warp] = v1; s_redd[2][warp] = v2; }
        __syncthreads();
        if (tid == 0) {
            double c0 = 0.0, c1 = 0.0, c2 = 0.0;
            #pragma unroll
            for (int w = 0; w < 8; w++) { c0 += s_redd[0][w]; c1 += s_redd[1][w]; c2 += s_redd[2][w]; }
            double loss_coord = 5.0 * c0;
            double loss_noobj = 0.5 * c2;
            double total = 5.0 * loss_coord + c1 + 0.5 * loss_noobj;
            if (out_size > 0) out[0] = (float)total;
            if (out_size > 1) out[1] = (float)loss_coord;
            if (out_size > 2) out[2] = (float)(c1 + loss_noobj);
            g_ticket = 0;   // reset for next graph replay
        }
    }
}

extern "C" void kernel_launch(void* const* d_in, const int* in_sizes, int n_in,
                              void* d_out, int out_size) {
    const float* pred = (const float*)d_in[0];   // [32,52,52,425]
    const float* tgt  = (const float*)d_in[1];   // [32,50,5]
    float* out = (float*)d_out;

    k_fused<<<NBLOCKS, 256>>>(pred, tgt, out, out_size);
}

// round 14
// speedup vs baseline: 1.0301x; 1.0226x over previous
#include <cuda_runtime.h>
#include <math.h>

// Problem constants
#define BB 32
#define SS 52
#define AA 5
#define CC 80
#define TT 50
#define PD (AA * (5 + CC))            // 425
#define NROWS (BB * SS * SS)          // 86,528
#define NCONF (NROWS * AA)            // 432,640
#define GG 2                          // confs per thread (front-batched)
#define NBLK_NOBJ (NCONF / (256 * GG))  // 845 (exact: 432640 = 845*512)
#define NBLOCKS (BB + NBLK_NOBJ)      // 877 : 0..31 targets, 32.. noobj

// Anchors (w, h)
__device__ __constant__ float c_anchors[AA * 2] = {
    1.3221f, 1.73145f,
    3.19275f, 4.00944f,
    5.05587f, 8.09892f,
    9.47112f, 4.84053f,
    11.2364f, 10.0071f
};

// Partials. Target blocks (0..31) write rows 0/1 + their g_part2 slot; noobj
// blocks write only g_part2. All read slots overwritten every launch.
__device__ float g_part0[BB];
__device__ float g_part1[BB];
__device__ float g_part2[NBLOCKS];
__device__ unsigned int g_ticket;   // static 0; finalizer resets

__device__ __forceinline__ float sigmoidf_(float x) {
    return 1.0f / (1.0f + __expf(-x));
}

__device__ __forceinline__ float warp_sum(float v) {
    #pragma unroll
    for (int o = 16; o > 0; o >>= 1) v += __shfl_down_sync(0xFFFFFFFFu, v, o);
    return v;
}
__device__ __forceinline__ double warp_sum_d(double v) {
    #pragma unroll
    for (int o = 16; o > 0; o >>= 1) v += __shfl_down_sync(0xFFFFFFFFu, v, o);
    return v;
}

__global__ __launch_bounds__(256) void k_fused(const float* __restrict__ pred,
                                               const float* __restrict__ tgt,
                                               float* __restrict__ out, int out_size) {
    __shared__ float s_t[TT * 5];       // target blocks only
    __shared__ int   s_cell[TT];
    __shared__ int   s_loser[TT];
    __shared__ float s_red[3][8];
    __shared__ double s_redd[3][8];
    __shared__ unsigned int s_last;

    const int tid = threadIdx.x;
    const int bid = blockIdx.x;
    const int lane = tid & 31, warp = tid >> 5;
    float a0 = 0.0f, a1 = 0.0f, a2 = 0.0f;   // coord, obj, conf^2 net

    if (bid < BB) {
        const int b = bid;
        if (tid < TT * 5) s_t[tid] = tgt[b * TT * 5 + tid];
        if (tid < TT) s_loser[tid] = 0;
        __syncthreads();

        // Per-target cell (threads 0..49)
        if (tid < TT) {
            const float* tr = &s_t[tid * 5];
            float gtw = tr[2] * (float)SS;
            float gth = tr[3] * (float)SS;
            float best = -1.0f;
            int best_a = 0;
            #pragma unroll
            for (int a = 0; a < AA; a++) {
                float aw = c_anchors[a * 2], ah = c_anchors[a * 2 + 1];
                float inter = fminf(gtw, aw) * fminf(gth, ah);
                float uni = gtw * gth + aw * ah - inter;
                float iou = (uni > 0.0f) ? (inter / uni) : 0.0f;
                if (iou > best) { best = iou; best_a = a; }  // first max wins
            }
            int gi = (int)(tr[0] * (float)SS);
            int gj = (int)(tr[1] * (float)SS);
            s_cell[tid] = (best_a * SS + gj) * SS + gi;      // batch-local cell id
        }
        __syncthreads();

        // Parallel last-wins: pair (t,u), u>t, same cell => t loses.
        for (int p = tid; p < TT * TT; p += 256) {
            int t = p / TT, u = p - t * TT;
            if (u > t && s_cell[u] == s_cell[t]) s_loser[t] = 1;
        }
        __syncthreads();

        // Winners gather + losses (threads 0..49)
        if (tid < TT && !s_loser[tid]) {
            const float* tr = &s_t[tid * 5];
            float gx = tr[0], gy = tr[1];
            float gtw = tr[2] * (float)SS;
            float gth = tr[3] * (float)SS;
            int myc = s_cell[tid];
            int gi = myc % SS;
            int gj = (myc / SS) % SS;
            int best_a = myc / (SS * SS);

            const float* p = pred + (((size_t)b * SS + gj) * SS + gi) * PD + best_a * (5 + CC);
            float tx = p[0], ty = p[1], tw = p[2], th = p[3], score = p[4];
            float pbx = sigmoidf_(tx);
            float pby = sigmoidf_(ty);
            float pbw = __expf(tw) * c_anchors[best_a * 2];
            float pbh = __expf(th) * c_anchors[best_a * 2 + 1];
            float conf = sigmoidf_(score);

            float ggx = gx * (float)SS - (float)gi;
            float ggy = gy * (float)SS - (float)gj;

            float cx1 = ggx + (float)gi, cy1 = ggy + (float)gj;
            float cx2 = pbx + (float)gi, cy2 = pby + (float)gj;
            float ix = fmaxf(0.0f, fminf(cx1 + gtw * 0.5f, cx2 + pbw * 0.5f)
                                 - fmaxf(cx1 - gtw * 0.5f, cx2 - pbw * 0.5f));
            float iy = fmaxf(0.0f, fminf(cy1 + gth * 0.5f, cy2 + pbh * 0.5f)
                                 - fmaxf(cy1 - gth * 0.5f, cy2 - pbh * 0.5f));
            float inter = ix * iy;
            float uni = gtw * gth + pbw * pbh - inter;
            float iou = (uni > 0.0f) ? (inter / uni) : 0.0f;

            const float eps = 1e-6f;
            float d1 = pbx - ggx, d2 = pby - ggy;
            float s1 = sqrtf(pbw + eps) - sqrtf(gtw + eps);
            float s2 = sqrtf(pbh + eps) - sqrtf(gth + eps);
            a0 = d1 * d1 + d2 * d2 + s1 * s1 + s2 * s2;
            float od = iou - conf;
            a1 = od * od;
            a2 = -conf * conf;      // remove obj cell from no-obj sum
        }
    } else {
        // No-obj: GG front-batched independent streaming loads per thread.
        int base = (bid - BB) * (256 * GG) + tid;   // stride-256 within block
        float s[GG];
        #pragma unroll
        for (int g = 0; g < GG; g++) {
            int n = base + g * 256;                 // < NCONF (exact tiling)
            int r = n / AA;
            int a = n - r * AA;
            s[g] = __ldcs(&pred[(size_t)r * PD + a * (5 + CC) + 4]);
        }
        #pragma unroll
        for (int g = 0; g < GG; g++) {
            float conf = sigmoidf_(s[g]);
            a2 += conf * conf;
        }
    }

    // Block reduction -> per-block partial slots (no atomics).
    // No-obj blocks only carry a2 -> slim single-value path.
    float w2 = warp_sum(a2);
    if (bid < BB) {
        float w0 = warp_sum(a0), w1 = warp_sum(a1);
        if (lane == 0) { s_red[0][warp] = w0; s_red[1][warp] = w1; }
    }
    if (lane == 0) s_red[2][warp] = w2;
    __syncthreads();
    if (tid == 0) {
        float b2 = 0.0f;
        #pragma unroll
        for (int w = 0; w < 8; w++) b2 += s_red[2][w];
        if (bid < BB) {
            float b0 = 0.0f, b1 = 0.0f;
            #pragma unroll
            for (int w = 0; w < 8; w++) { b0 += s_red[0][w]; b1 += s_red[1][w]; }
            g_part0[bid] = b0;
            g_part1[bid] = b1;
        }
        g_part2[bid] = b2;
        __threadfence();
        unsigned int t = atomicAdd(&g_ticket, 1u);
        s_last = (t == (unsigned int)(gridDim.x - 1)) ? 1u : 0u;
    }
    __syncthreads();

    // Parallel finalize in last-arriving block (fixed-order -> deterministic)
    if (s_last) {
        double v0 = 0.0, v1 = 0.0, v2 = 0.0;
        if (tid < BB) { v0 = (double)g_part0[tid]; v1 = (double)g_part1[tid]; }
        for (int i = tid; i < NBLOCKS; i += 256) v2 += (double)g_part2[i];
        v0 = warp_sum_d(v0); v1 = warp_sum_d(v1); v2 = warp_sum_d(v2);
        if (lane == 0) { s_redd[0][warp] = v0; s_redd[1][warp] = v1; s_redd[2][warp] = v2; }
        __syncthreads();
        if (tid == 0) {
            double c0 = 0.0, c1 = 0.0, c2 = 0.0;
            #pragma unroll
            for (int w = 0; w < 8; w++) { c0 += s_redd[0][w]; c1 += s_redd[1][w]; c2 += s_redd[2][w]; }
            double loss_coord = 5.0 * c0;
            double loss_noobj = 0.5 * c2;
            double total = 5.0 * loss_coord + c1 + 0.5 * loss_noobj;
            if (out_size > 0) out[0] = (float)total;
            if (out_size > 1) out[1] = (float)loss_coord;
            if (out_size > 2) out[2] = (float)(c1 + loss_noobj);
            g_ticket = 0;   // reset for next graph replay
        }
    }
}

extern "C" void kernel_launch(void* const* d_in, const int* in_sizes, int n_in,
                              void* d_out, int out_size) {
    const float* pred = (const float*)d_in[0];   // [32,52,52,425]
    const float* tgt  = (const float*)d_in[1];   // [32,50,5]
    float* out = (float*)d_out;

    k_fused<<<NBLOCKS, 256>>>(pred, tgt, out, out_size);
}